// round 13
// baseline (speedup 1.0000x reference)
#include <cuda_runtime.h>
#include <math.h>

#define BATCH 256
#define NN    1024
#define PP    128
#define DIN   784
#define COUT  10
#define CH    32                     /* columns per CTA */
#define NEV   64                     /* RK4 evals */
#define NGRP  8                      /* row groups (blockIdx.y) */
#define GXS   32                     /* CTAs per group (blockIdx.x) */

#define TWO_PI_F 6.283185307179586f
#define DT       0.03125f
#define BETA_N   (2.0f/1024.0f)
#define A_ANC    0.08f
#define OME      (TWO_PI_F*200.0f)

typedef unsigned long long ull;
typedef unsigned int uint;

__device__ __forceinline__ ull pack2(float a, float b) {
    ull r; asm("mov.b64 %0,{%1,%2};" : "=l"(r) : "f"(a), "f"(b)); return r;
}
__device__ __forceinline__ ull fma2(ull a, ull b, ull c) {
    ull d; asm("fma.rn.f32x2 %0,%1,%2,%3;" : "=l"(d) : "l"(a), "l"(b), "l"(c));
    return d;
}
__device__ __forceinline__ uint bf2(float lo, float hi) {
    uint d; asm("cvt.rn.bf16x2.f32 %0,%1,%2;" : "=r"(d) : "f"(hi), "f"(lo));
    return d;                         /* lower 16 bits = lo */
}
__device__ __forceinline__ unsigned su32(const void* p) {
    return (unsigned)__cvta_generic_to_shared(p);
}
#define CP16(dst, src) \
    asm volatile("cp.async.cg.shared.global [%0], [%1], 16;" :: "r"(dst), "l"(src))
#define CP_COMMIT() asm volatile("cp.async.commit_group;")
#define CP_WAIT(n)  asm volatile("cp.async.wait_group %0;" :: "n"(n))

#define MMA_BF16(d0,d1,d2,d3,a0,a1,a2,a3,b0,b1) \
    asm volatile("mma.sync.aligned.m16n8k16.row.col.f32.bf16.bf16.f32 " \
        "{%0,%1,%2,%3}, {%4,%5,%6,%7}, {%8,%9}, {%0,%1,%2,%3};" \
        : "+f"(d0), "+f"(d1), "+f"(d2), "+f"(d3) \
        : "r"(a0), "r"(a1), "r"(a2), "r"(a3), "r"(b0), "r"(b1))

struct EvalConsts { float sA[NEV]; float cA[NEV]; float cN[NEV]; };

/* ---- device scratch ---- */
__device__ float g_xc[PP*NN];
__device__ float g_xs[PP*NN];
__device__ float g_phi[BATCH*NN];
__device__ float g_fc[BATCH*NN];
__device__ float g_fs[BATCH*NN];
__device__ float g_m[3][BATCH*PP];
__device__ unsigned g_cnt[NGRP*NEV];

/* ---- k_run shared layout (floats) ----
   sW   [0,     4160)   w tile [32][130]
   sXC  [4160,  8768)   [128][36] fp32
   sXS  [8768, 13376)
   bfC  [13376,14016)   [32][40] bf16  (640 floats = 320 words*2... 32*20 words)
   bfS  [14016,14656)
   xcb  [14656,17216)   [128][40] bf16 (2560 floats)
   xsb  [17216,19776)
   sR   [19776,24896)   256 writers x 20 floats; [0,4096) = m prefetch     */
#define SW_STRIDE 130
#define SX_STRIDE 36
#define SW_FLOATS 4160
#define SX_FLOATS 4608
#define OFF_BFC   13376
#define OFF_BFS   14016
#define OFF_XCB   14656
#define OFF_XSB   17216
#define OFF_SR    19776
#define SR_STRIDE 20
#define SMEM_FLOATS 24896
#define SMEM_BYTES  (SMEM_FLOATS*4)   /* 99584 -> 2 CTAs/SM */

/* encoder-private extra regions (reuse area past sXS) */
#define ENC_SC 13376
#define ENC_SS 14528                  /* [32][36] each */

/* ================= init ================================================= */
__global__ void k_init(const float* __restrict__ xi) {
    int i = blockIdx.x*256 + threadIdx.x;
    if (i < PP*NN) {
        float v = xi[i];
        g_xc[i] = cosf(v);
        g_xs[i] = sinf(v);
    }
    if (i < BATCH*PP) { g_m[0][i] = 0.f; g_m[1][i] = 0.f; }
    if (i < NGRP*NEV) g_cnt[i] = 0u;
}

__device__ __forceinline__ void load_xtiles(float* sXC, float* sXS, int n0) {
    for (int i = threadIdx.x; i < 128*8; i += 256) {
        int p = i >> 3, q = (i & 7) << 2;
        float4 a = *(const float4*)&g_xc[p*NN + n0 + q];
        *(float4*)&sXC[p*SX_STRIDE + q] = a;
        float4 b = *(const float4*)&g_xs[p*NN + n0 + q];
        *(float4*)&sXS[p*SX_STRIDE + q] = b;
    }
}

/* scalar fma2 m_tail (encoder only; 4r x 4p, register-light) */
__device__ __forceinline__ void m_tail_enc(const float* sC, const float* sS,
                                           const float* sXC, const float* sXS,
                                           float* mbuf, int r0) {
    int rb = threadIdx.x >> 5;
    int pb = threadIdx.x & 31;
    ull acc[16];
#pragma unroll
    for (int i = 0; i < 16; i++) acc[i] = 0ull;
    const float* cB  = sC  + (rb*4)*SX_STRIDE;
    const float* sB  = sS  + (rb*4)*SX_STRIDE;
    const float* xcB = sXC + pb*SX_STRIDE;
    const float* xsB = sXS + pb*SX_STRIDE;
#pragma unroll
    for (int nn = 0; nn < CH; nn += 4) {
        ulonglong2 cr[4], sr[4];
#pragma unroll
        for (int r = 0; r < 4; r++) {
            cr[r] = *(const ulonglong2*)&cB[r*SX_STRIDE + nn];
            sr[r] = *(const ulonglong2*)&sB[r*SX_STRIDE + nn];
        }
#pragma unroll
        for (int j = 0; j < 4; j++) {
            ulonglong2 xc2 = *(const ulonglong2*)&xcB[j*32*SX_STRIDE + nn];
            ulonglong2 xs2 = *(const ulonglong2*)&xsB[j*32*SX_STRIDE + nn];
#pragma unroll
            for (int r = 0; r < 4; r++) {
                ull a = acc[j*4 + r];
                a = fma2(cr[r].x, xc2.x, a);
                a = fma2(cr[r].y, xc2.y, a);
                a = fma2(sr[r].x, xs2.x, a);
                a = fma2(sr[r].y, xs2.y, a);
                acc[j*4 + r] = a;
            }
        }
    }
#pragma unroll
    for (int j = 0; j < 4; j++)
#pragma unroll
        for (int r = 0; r < 4; r++) {
            float lo, hi;
            asm("mov.b64 {%0,%1},%2;" : "=f"(lo), "=f"(hi) : "l"(acc[j*4+r]));
            atomicAdd(&mbuf[(r0 + rb*4 + r)*PP + pb + 32*j], lo + hi);
        }
}

/* ================= encoder ============================================== */
__global__ void __launch_bounds__(256, 2)
k_encoder(const float* __restrict__ x,
          const float* __restrict__ Wenc,
          const float* __restrict__ benc) {
    extern __shared__ float sm[];
    float* sA  = sm;
    float* sB  = sm + 32*17;
    float* sXC = sm + SW_FLOATS;
    float* sXS = sXC + SX_FLOATS;
    float* sC  = sm + ENC_SC;
    float* sS  = sm + ENC_SS;

    int n0 = blockIdx.x*CH, r0 = blockIdx.y*32;
    int tid = threadIdx.x;
    int row = tid >> 3, ng = tid & 7, nb = ng*4;

    float acc[4];
#pragma unroll
    for (int i = 0; i < 4; i++) acc[i] = 0.f;

    for (int d0 = 0; d0 < DIN; d0 += 16) {
        for (int i = tid; i < 512; i += 256) {
            int r = i >> 4, j = i & 15;
            sA[r*17 + j] = x[(r0+r)*DIN + d0 + j];
            sB[r*17 + j] = Wenc[(n0+r)*DIN + d0 + j];
        }
        __syncthreads();
#pragma unroll
        for (int j = 0; j < 16; j++) {
            float xa = sA[row*17 + j];
#pragma unroll
            for (int i = 0; i < 4; i++) acc[i] += xa * sB[(nb+i)*17 + j];
        }
        __syncthreads();
    }

    load_xtiles(sXC, sXS, n0);

#pragma unroll
    for (int i = 0; i < 4; i++) {
        float z  = acc[i] + benc[n0 + nb + i];
        float p0 = TWO_PI_F / (1.0f + expf(-z));
        int gi = (r0+row)*NN + n0 + nb + i;
        g_phi[gi]  = p0;
        float ss, cc;
        __sincosf(p0, &ss, &cc);
        g_fc[gi] = cc;
        g_fs[gi] = ss;
        sC[row*SX_STRIDE + nb + i] = cc;
        sS[row*SX_STRIDE + nb + i] = ss;
    }
    __syncthreads();
    m_tail_enc(sC, sS, sXC, sXS, g_m[0], r0);
}

/* ================= persistent RK4 kernel ================================ */
__global__ void __launch_bounds__(256, 2)
k_run(EvalConsts ec) {
    extern __shared__ float sm[];
    float* sW  = sm;
    float* sXC = sm + SW_FLOATS;
    float* sXS = sXC + SX_FLOATS;
    uint*  bCw = (uint*)(sm + OFF_BFC);   /* [32][20] words bf16x2 */
    uint*  bSw = (uint*)(sm + OFF_BFS);
    uint*  xcbW= (uint*)(sm + OFF_XCB);   /* [128][20] words       */
    uint*  xsbW= (uint*)(sm + OFF_XSB);
    float* sR  = sm + OFF_SR;

    int n0 = blockIdx.x*CH, r0 = blockIdx.y*32;
    int tid = threadIdx.x;
    int row = tid >> 3, cf = tid & 7;
    int gso = (r0+row)*NN + n0 + cf*4;
    int cta = blockIdx.y*GXS + blockIdx.x;
    int grp = blockIdx.y;
    int warp = tid >> 5, lane = tid & 31;

    /* ---- one-time: xi tiles + feature registers ---- */
#pragma unroll
    for (int it = 0; it < 4; it++) {
        int i = tid + it*256;
        int p = i >> 3, q = (i & 7) << 2;
        CP16(su32(&sXC[p*SX_STRIDE + q]), &g_xc[p*NN + n0 + q]);
        CP16(su32(&sXS[p*SX_STRIDE + q]), &g_xs[p*NN + n0 + q]);
    }
    CP_COMMIT();

    float4 fc0 = *(const float4*)&g_fc[gso];
    float4 fs0 = *(const float4*)&g_fs[gso];
    float ce[4] = {fc0.x, fc0.y, fc0.z, fc0.w};
    float se[4] = {fs0.x, fs0.y, fs0.z, fs0.w};
    float4 p00 = *(const float4*)&g_phi[gso];
    float ph[4] = {p00.x, p00.y, p00.z, p00.w};
    float av[4] = {0.f, 0.f, 0.f, 0.f};

    CP_WAIT(0);
    __syncthreads();
    /* build bf16 xi tiles [p][k]: thread -> p = tid>>1, khalf = tid&1 */
    {
        int p = tid >> 1, kh = (tid & 1)*16;
        const float* xc = &sXC[p*SX_STRIDE + kh];
        const float* xs = &sXS[p*SX_STRIDE + kh];
        uint* dc = &xcbW[p*20 + (kh >> 1)];
        uint* ds = &xsbW[p*20 + (kh >> 1)];
#pragma unroll
        for (int i = 0; i < 8; i++) {
            dc[i] = bf2(xc[2*i], xc[2*i+1]);
            ds[i] = bf2(xs[2*i], xs[2*i+1]);
        }
    }
    __syncthreads();

    for (int e = 0; e < NEV; e++) {
        int sub  = e & 3;
        int bufR = e % 3, bufW = (e + 1) % 3, bufZ = (e + 2) % 3;
        float sAnc = ec.sA[e], cAnc = ec.cA[e], cNext = ec.cN[e];

        /* prefetch m slice into sR[0,4096) */
        {
            const float* gmp = &g_m[bufR][(r0+row)*PP + cf*16];
            unsigned d = su32(&sR[row*PP + cf*16]);
            CP16(d,      gmp);
            CP16(d + 16, gmp + 4);
            CP16(d + 32, gmp + 8);
            CP16(d + 48, gmp + 12);
        }
        CP_COMMIT();

        if (tid < 128) g_m[bufZ][cta*128 + tid] = 0.f;

        CP_WAIT(0);
        /* ---- softmax (arg in [-2,2]) ---- */
        {
            const float* mrow = &sR[row*PP + cf*16];
            float a[16];
            float ssum = 0.f;
#pragma unroll
            for (int j = 0; j < 16; j++) {
                a[j] = __expf(mrow[j] * BETA_N);
                ssum += a[j];
            }
#pragma unroll
            for (int w = 1; w < 8; w <<= 1)
                ssum += __shfl_xor_sync(0xffffffffu, ssum, w);
            float inv = 1.0f / ssum;
#pragma unroll
            for (int j = 0; j < 16; j++)
                sW[row*SW_STRIDE + cf*16 + j] = a[j] * inv;
        }
        __syncthreads();

        /* ---- coupling GEMM fp32 fma2: tile 2r x 4c, K-split 2 ---- */
        {
            int ks = tid >> 7;
            int t7 = tid & 127;
            int rp = t7 >> 3;
            int cg = t7 & 7;
            ull aC0a=0, aC0b=0, aC1a=0, aC1b=0;
            ull aS0a=0, aS0b=0, aS1a=0, aS1b=0;
            const float* w0 = &sW[(rp*2)*SW_STRIDE + ks*64];
            const float* w1 = w0 + SW_STRIDE;
            const float* xc = &sXC[(ks*64)*SX_STRIDE + cg*4];
            const float* xs = &sXS[(ks*64)*SX_STRIDE + cg*4];
#pragma unroll 4
            for (int p = 0; p < 64; p++) {
                ulonglong2 c2 = *(const ulonglong2*)xc;
                ulonglong2 s2 = *(const ulonglong2*)xs;
                xc += SX_STRIDE; xs += SX_STRIDE;
                float wa = w0[p], wb = w1[p];
                ull wpa = pack2(wa, wa), wpb = pack2(wb, wb);
                aC0a = fma2(wpa, c2.x, aC0a); aC0b = fma2(wpa, c2.y, aC0b);
                aC1a = fma2(wpb, c2.x, aC1a); aC1b = fma2(wpb, c2.y, aC1b);
                aS0a = fma2(wpa, s2.x, aS0a); aS0b = fma2(wpa, s2.y, aS0b);
                aS1a = fma2(wpb, s2.x, aS1a); aS1b = fma2(wpb, s2.y, aS1b);
            }
            float* rr = &sR[tid*SR_STRIDE];
            *(ull*)&rr[0]  = aC0a; *(ull*)&rr[2]  = aC0b;
            *(ull*)&rr[4]  = aC1a; *(ull*)&rr[6]  = aC1b;
            *(ull*)&rr[8]  = aS0a; *(ull*)&rr[10] = aS0b;
            *(ull*)&rr[12] = aS1a; *(ull*)&rr[14] = aS1b;
        }
        __syncthreads();

        /* ---- reduce + elementwise (features live in registers) ---- */
        {
            int wr = (row >> 1)*8 + cf;          /* writer tile id 0..127 */
            int ib = (row & 1)*4;
            float wc4[4], ws4[4];
            {
                const float* ra = &sR[wr*SR_STRIDE];
                const float* rb = &sR[(128 + wr)*SR_STRIDE];
                float4 c0 = *(const float4*)&ra[ib];
                float4 c1 = *(const float4*)&rb[ib];
                float4 s0 = *(const float4*)&ra[8 + ib];
                float4 s1 = *(const float4*)&rb[8 + ib];
                wc4[0] = c0.x + c1.x; wc4[1] = c0.y + c1.y;
                wc4[2] = c0.z + c1.z; wc4[3] = c0.w + c1.w;
                ws4[0] = s0.x + s1.x; ws4[1] = s0.y + s1.y;
                ws4[2] = s0.z + s1.z; ws4[3] = s0.w + s1.w;
            }

            float kv[4];
#pragma unroll
            for (int j = 0; j < 4; j++)
                kv[j] = fmaf(se[j], wc4[j] - cAnc, ce[j] * (sAnc - ws4[j]));

            float phiN[4];
            if (sub == 0) {
#pragma unroll
                for (int j = 0; j < 4; j++) {
                    av[j] = kv[j];
                    phiN[j] = fmaf(cNext, kv[j], ph[j]);
                }
            } else if (sub == 3) {
#pragma unroll
                for (int j = 0; j < 4; j++) {
                    ph[j] = fmaf(DT/6.0f, av[j] + kv[j], ph[j]);
                    phiN[j] = ph[j];
                }
            } else {
#pragma unroll
                for (int j = 0; j < 4; j++) {
                    av[j] = fmaf(2.0f, kv[j], av[j]);
                    phiN[j] = fmaf(cNext, kv[j], ph[j]);
                }
            }

            if (e < NEV-1) {
#pragma unroll
                for (int j = 0; j < 4; j++)
                    __sincosf(phiN[j], &se[j], &ce[j]);
                int wbase = row*20 + cf*2;
                bCw[wbase]     = bf2(ce[0], ce[1]);
                bCw[wbase + 1] = bf2(ce[2], ce[3]);
                bSw[wbase]     = bf2(se[0], se[1]);
                bSw[wbase + 1] = bf2(se[2], se[3]);
            }
        }

        if (e < NEV-1) {
            __syncthreads();
            /* ---- m_tail via bf16 MMA: warp -> 16 rows x 32 pats ---- */
            {
                int rh = (warp & 1)*16;
                int pn = (warp >> 1)*32;
                float d[4][4];
#pragma unroll
                for (int nt = 0; nt < 4; nt++)
#pragma unroll
                    for (int i = 0; i < 4; i++) d[nt][i] = 0.f;

#pragma unroll
                for (int g = 0; g < 2; g++) {
                    const uint* A = g ? bSw : bCw;
                    const uint* B = g ? xsbW : xcbW;
#pragma unroll
                    for (int kk = 0; kk < 2; kk++) {
                        int ab = (rh + (lane >> 2))*20 + (lane & 3) + kk*8;
                        uint a0 = A[ab];
                        uint a1 = A[ab + 160];
                        uint a2 = A[ab + 4];
                        uint a3 = A[ab + 164];
#pragma unroll
                        for (int nt = 0; nt < 4; nt++) {
                            int bb = (pn + nt*8 + (lane >> 2))*20
                                   + (lane & 3) + kk*8;
                            uint b0 = B[bb];
                            uint b1 = B[bb + 4];
                            MMA_BF16(d[nt][0], d[nt][1], d[nt][2], d[nt][3],
                                     a0, a1, a2, a3, b0, b1);
                        }
                    }
                }
                float* mbuf = g_m[bufW];
                int r  = r0 + rh + (lane >> 2);
                int pb = pn + 2*(lane & 3);
#pragma unroll
                for (int nt = 0; nt < 4; nt++) {
                    atomicAdd(&mbuf[r*PP + pb + nt*8],       d[nt][0]);
                    atomicAdd(&mbuf[r*PP + pb + nt*8 + 1],   d[nt][1]);
                    atomicAdd(&mbuf[(r+8)*PP + pb + nt*8],   d[nt][2]);
                    atomicAdd(&mbuf[(r+8)*PP + pb + nt*8+1], d[nt][3]);
                }
            }
            /* ---- group barrier ---- */
            __syncthreads();
            if (tid == 0) {
                __threadfence();
                atomicAdd(&g_cnt[grp*NEV + e], 1u);
                volatile unsigned* c = &g_cnt[grp*NEV + e];
                while (*c < (unsigned)GXS) { }
                __threadfence();
            }
            __syncthreads();
        }
    }

    /* ---- write back final phi ---- */
    *(float4*)&g_phi[gso] = make_float4(ph[0], ph[1], ph[2], ph[3]);
}

/* ================= readout ============================================== */
__global__ void __launch_bounds__(256)
k_readout(const float* __restrict__ Wout,
          const float* __restrict__ bout,
          float* __restrict__ out) {
    __shared__ float red[8*2*COUT];
    int b0 = blockIdx.x*2, tid = threadIdx.x;
    int n4 = tid*4;

    float4 pa = *(const float4*)&g_phi[b0*NN + n4];
    float4 pb = *(const float4*)&g_phi[(b0+1)*NN + n4];
    float pha[4] = {pa.x, pa.y, pa.z, pa.w};
    float phb[4] = {pb.x, pb.y, pb.z, pb.w};
    float ca[4], sa[4], cb[4], sb[4];
#pragma unroll
    for (int j = 0; j < 4; j++) {
        sincosf(pha[j], &sa[j], &ca[j]);
        sincosf(phb[j], &sb[j], &cb[j]);
    }

    float acc[2][COUT];
#pragma unroll
    for (int cls = 0; cls < COUT; cls++) {
        float4 wcv = *(const float4*)&Wout[cls*(2*NN) + n4];
        float4 wsv = *(const float4*)&Wout[cls*(2*NN) + NN + n4];
        float a0 = ca[0]*wcv.x + sa[0]*wsv.x;
        a0 = fmaf(ca[1], wcv.y, a0); a0 = fmaf(sa[1], wsv.y, a0);
        a0 = fmaf(ca[2], wcv.z, a0); a0 = fmaf(sa[2], wsv.z, a0);
        a0 = fmaf(ca[3], wcv.w, a0); a0 = fmaf(sa[3], wsv.w, a0);
        acc[0][cls] = a0;
        float a1 = cb[0]*wcv.x + sb[0]*wsv.x;
        a1 = fmaf(cb[1], wcv.y, a1); a1 = fmaf(sb[1], wsv.y, a1);
        a1 = fmaf(cb[2], wcv.z, a1); a1 = fmaf(sb[2], wsv.z, a1);
        a1 = fmaf(cb[3], wcv.w, a1); a1 = fmaf(sb[3], wsv.w, a1);
        acc[1][cls] = a1;
    }
#pragma unroll
    for (int rr = 0; rr < 2; rr++)
#pragma unroll
        for (int cls = 0; cls < COUT; cls++)
#pragma unroll
            for (int w = 16; w > 0; w >>= 1)
                acc[rr][cls] += __shfl_xor_sync(0xffffffffu, acc[rr][cls], w);

    int warp = tid >> 5, lane = tid & 31;
    if (lane == 0)
#pragma unroll
        for (int rr = 0; rr < 2; rr++)
#pragma unroll
            for (int cls = 0; cls < COUT; cls++)
                red[warp*2*COUT + rr*COUT + cls] = acc[rr][cls];
    __syncthreads();

    if (tid < 2*COUT) {
        int rr = tid / COUT, cls = tid % COUT;
        float t = bout[cls];
#pragma unroll
        for (int w = 0; w < 8; w++) t += red[w*2*COUT + rr*COUT + cls];
        out[(b0+rr)*COUT + cls] = t;
    }
}

/* ================= host ================================================= */
extern "C" void kernel_launch(void* const* d_in, const int* in_sizes, int n_in,
                              void* d_out, int out_size) {
    (void)in_sizes; (void)n_in; (void)out_size;
    const float* x    = (const float*)d_in[0];
    const float* Wenc = (const float*)d_in[1];
    const float* benc = (const float*)d_in[2];
    const float* xi   = (const float*)d_in[3];
    const float* Wout = (const float*)d_in[4];
    const float* bout = (const float*)d_in[5];
    float* out = (float*)d_out;

    cudaFuncSetAttribute(k_encoder, cudaFuncAttributeMaxDynamicSharedMemorySize, SMEM_BYTES);
    cudaFuncSetAttribute(k_run,     cudaFuncAttributeMaxDynamicSharedMemorySize, SMEM_BYTES);

    EvalConsts ec;
    for (int e = 0; e < NEV; e++) {
        int step = e >> 2, sub = e & 3;
        float t0 = (float)step * DT;
        float tE = (sub == 0) ? t0 : ((sub == 3) ? t0 + DT : t0 + 0.5f*DT);
        float argf = OME * tE;
        double sa = sin((double)argf), ca = cos((double)argf);
        ec.sA[e] = (float)((double)A_ANC * sa);
        ec.cA[e] = (float)((double)A_ANC * ca);
        ec.cN[e] = (sub == 2) ? DT : 0.5f*DT;
    }

    k_init<<<512, 256>>>(xi);

    dim3 grid(GXS, NGRP);
    k_encoder<<<grid, 256, SMEM_BYTES>>>(x, Wenc, benc);
    k_run<<<grid, 256, SMEM_BYTES>>>(ec);
    k_readout<<<BATCH/2, 256>>>(Wout, bout, out);
}